// round 15
// baseline (speedup 1.0000x reference)
#include <cuda_runtime.h>
#include <cuda_fp16.h>

typedef unsigned int uint;

static constexpr int   T = 262144;
static constexpr int   S = 128;
static constexpr int   H = 1024;
static constexpr int   A = 16;
static constexpr float GAMMA = 0.99f;
static constexpr float EPSC  = 0.2f;
static constexpr float LOG_SQRT_2PI = 0.91893853320467274178f;

// ---------------- device scratch (no allocation allowed) ----------------
__device__ float g_adv[T];
__device__ float g_blockA[256];
__device__ float g_blockB[256];
__device__ float g_s1, g_s2, g_actor;
__device__ float g_mean, g_inv, g_critic;
__device__ uint  g_cnt_scan, g_cnt_main;
__device__ __half g_W1h[S * H];     // [k][h]  fp16 copy of W1
__device__ __half g_Wmh[H * A];     // [h][a]
__device__ __half g_Wlh[H * A];     // [h][a]
__device__ uint   g_b1h[H / 2];     // b1 packed as half2 pairs

// ---------------- helpers ----------------
__device__ __forceinline__ uint smem_u32(const void* p) {
    uint a;
    asm("{ .reg .u64 t; cvta.to.shared.u64 t, %1; cvt.u32.u64 %0, t; }" : "=r"(a) : "l"(p));
    return a;
}

#define CP_ASYNC16(dst, src) \
    asm volatile("cp.async.cg.shared.global [%0], [%1], 16;" :: "r"(dst), "l"(src))
#define CP_COMMIT() asm volatile("cp.async.commit_group;" ::: "memory")
#define CP_WAIT1()  asm volatile("cp.async.wait_group 1;" ::: "memory")
#define CP_WAIT0()  asm volatile("cp.async.wait_group 0;" ::: "memory")

#define LDSM_X4(r0, r1, r2, r3, addr) \
    asm volatile("ldmatrix.sync.aligned.m8n8.x4.shared.b16 {%0,%1,%2,%3}, [%4];" \
        : "=r"(r0), "=r"(r1), "=r"(r2), "=r"(r3) : "r"(addr))
#define LDSM_X4T(r0, r1, r2, r3, addr) \
    asm volatile("ldmatrix.sync.aligned.m8n8.x4.trans.shared.b16 {%0,%1,%2,%3}, [%4];" \
        : "=r"(r0), "=r"(r1), "=r"(r2), "=r"(r3) : "r"(addr))

// fp32-accumulate mma (GEMM2)
#define MMA16816(d, a, b0, b1) \
    asm volatile("mma.sync.aligned.m16n8k16.row.col.f32.f16.f16.f32 " \
        "{%0,%1,%2,%3}, {%4,%5,%6,%7}, {%8,%9}, {%0,%1,%2,%3};" \
        : "+f"((d)[0]), "+f"((d)[1]), "+f"((d)[2]), "+f"((d)[3]) \
        : "r"((a)[0]), "r"((a)[1]), "r"((a)[2]), "r"((a)[3]), "r"(b0), "r"(b1))

// fp16-accumulate mma (GEMM1; fewer acc regs)
#define MMA16816H(d, a, b0, b1) \
    asm volatile("mma.sync.aligned.m16n8k16.row.col.f16.f16.f16.f16 " \
        "{%0,%1}, {%2,%3,%4,%5}, {%6,%7}, {%0,%1};" \
        : "+r"((d)[0]), "+r"((d)[1]) \
        : "r"((a)[0]), "r"((a)[1]), "r"((a)[2]), "r"((a)[3]), "r"(b0), "r"(b1))

__device__ __forceinline__ uint htanh2(uint x) {
    uint y; asm("tanh.approx.f16x2 %0, %1;" : "=r"(y) : "r"(x)); return y;
}
__device__ __forceinline__ uint hadd2u(uint x, uint y) {
    uint z; asm("add.f16x2 %0, %1, %2;" : "=r"(z) : "r"(x), "r"(y)); return z;
}

// ---------------- Kp: pre-convert weights + pack b1 + zero accumulators ------
__global__ void k_prep(const float* __restrict__ W1, const float* __restrict__ Wmu,
                       const float* __restrict__ Wlv, const float* __restrict__ b1) {
    int idx = blockIdx.x * 256 + threadIdx.x;     // 0 .. 131071
    g_W1h[idx] = __float2half_rn(W1[idx]);
    if (idx < H * A) {
        g_Wmh[idx] = __float2half_rn(Wmu[idx]);
        g_Wlh[idx] = __float2half_rn(Wlv[idx]);
    }
    if (idx < H / 2) {
        half2 p = __floats2half2_rn(b1[2 * idx], b1[2 * idx + 1]);
        g_b1h[idx] = *(uint*)&p;
    }
    if (idx == 0) {
        g_s1 = 0.f; g_s2 = 0.f; g_actor = 0.f;
        g_cnt_scan = 0u; g_cnt_main = 0u;
    }
}

// ---------------- K1: per-block affine composition (Kogge-Stone) ----------------
__global__ void k_scan1(const float* __restrict__ rewards, const int* __restrict__ masks) {
    int blk = blockIdx.x, tid = threadIdx.x;
    int base = blk * 1024 + tid * 4;
    float4 r = *(const float4*)(rewards + base);
    int4   m = *(const int4*)(masks + base);
    float a = 1.f, b = 0.f, c;
    c = GAMMA * (float)m.w; b = r.w + c * b; a *= c;
    c = GAMMA * (float)m.z; b = r.z + c * b; a *= c;
    c = GAMMA * (float)m.y; b = r.y + c * b; a *= c;
    c = GAMMA * (float)m.x; b = r.x + c * b; a *= c;
    __shared__ float sA[256], sB[256];
    sA[tid] = a; sB[tid] = b;
    __syncthreads();
    #pragma unroll
    for (int o = 1; o < 256; o <<= 1) {
        float na = a, nb = b;
        if (tid + o < 256) { na = a * sA[tid + o]; nb = b + a * sB[tid + o]; }
        __syncthreads();
        sA[tid] = na; sB[tid] = nb; a = na; b = nb;
        __syncthreads();
    }
    if (tid == 0) { g_blockA[blk] = a; g_blockB[blk] = b; }
}

// ---------------- K2: apply scan + adv + sums + (last block) stats ----------------
__global__ void k_scan3(const float* __restrict__ rewards, const int* __restrict__ masks,
                        const float* __restrict__ values) {
    int blk = blockIdx.x, tid = threadIdx.x;
    int base = blk * 1024 + tid * 4;
    float4 r = *(const float4*)(rewards + base);
    int4   m = *(const int4*)(masks + base);
    float c0 = GAMMA * (float)m.x, c1 = GAMMA * (float)m.y;
    float c2 = GAMMA * (float)m.z, c3 = GAMMA * (float)m.w;
    float a = 1.f, b = 0.f;
    b = r.w + c3 * b; a *= c3;
    b = r.z + c2 * b; a *= c2;
    b = r.y + c1 * b; a *= c1;
    b = r.x + c0 * b; a *= c0;

    __shared__ float sA[256], sB[256];
    __shared__ float red8[8];

    float ga = g_blockA[tid], gb = g_blockB[tid];
    sA[tid] = ga; sB[tid] = gb;
    __syncthreads();
    #pragma unroll
    for (int o = 1; o < 256; o <<= 1) {
        float na = ga, nb = gb;
        if (tid + o < 256) { na = ga * sA[tid + o]; nb = gb + ga * sB[tid + o]; }
        __syncthreads();
        sA[tid] = na; sB[tid] = nb; ga = na; gb = nb;
        __syncthreads();
    }
    float inc = (blk < 255) ? sB[blk + 1] : 0.f;
    __syncthreads();

    float qa = a, qb = b;
    sA[tid] = qa; sB[tid] = qb;
    __syncthreads();
    #pragma unroll
    for (int o = 1; o < 256; o <<= 1) {
        float na = qa, nb = qb;
        if (tid + o < 256) { na = qa * sA[tid + o]; nb = qb + qa * sB[tid + o]; }
        __syncthreads();
        sA[tid] = na; sB[tid] = nb; qa = na; qb = nb;
        __syncthreads();
    }
    float x = (tid < 255) ? (sA[tid + 1] * inc + sB[tid + 1]) : inc;

    float ret3 = r.w + c3 * x;
    float ret2 = r.z + c2 * ret3;
    float ret1 = r.y + c1 * ret2;
    float ret0 = r.x + c0 * ret1;
    float4 v = *(const float4*)(values + base);
    float4 adv = make_float4(ret0 - v.x, ret1 - v.y, ret2 - v.z, ret3 - v.w);
    *(float4*)(g_adv + base) = adv;
    float s1 = adv.x + adv.y + adv.z + adv.w;
    float s2 = adv.x * adv.x + adv.y * adv.y + adv.z * adv.z + adv.w * adv.w;

    #pragma unroll
    for (int o = 16; o > 0; o >>= 1) {
        s1 += __shfl_down_sync(0xffffffffu, s1, o);
        s2 += __shfl_down_sync(0xffffffffu, s2, o);
    }
    if ((tid & 31) == 0) { red8[tid >> 5] = s1; }
    __syncthreads();
    if ((tid & 31) == 0) { sA[tid >> 5] = s2; }
    __syncthreads();
    if (tid == 0) {
        float t1 = 0.f, t2 = 0.f;
        #pragma unroll
        for (int i = 0; i < 8; ++i) { t1 += red8[i]; t2 += sA[i]; }
        atomicAdd(&g_s1, t1);
        atomicAdd(&g_s2, t2);
        __threadfence();
        uint done = atomicAdd(&g_cnt_scan, 1u);
        if (done == 255u) {
            float S1 = atomicAdd(&g_s1, 0.f);
            float S2 = atomicAdd(&g_s2, 0.f);
            float mean = S1 / (float)T;
            float var  = (S2 - S1 * mean) / (float)(T - 1);
            g_mean = mean;
            g_inv  = 1.f / (sqrtf(var) + 1e-7f);
            g_critic = S2 / (float)T;
        }
    }
}

// ---------------- K5: 3 CTAs/SM; one-stage software-pipelined LDSM->MMA --------
static constexpr int RT  = 128;      // rows per CTA (4 warps x 32 rows)
static constexpr int NCH = 32;       // H chunks of 32
static constexpr int LDA = 136;      // A staging stride (halves)
static constexpr int LDW = 40;       // W1 smem stride (halves) for 32-col chunk
static constexpr int LD2 = 24;       // W2 smem stride (halves)
static constexpr int LDMU = 20;      // mu/lv overlay stride (floats)

static constexpr int SM_W1    = 0;                      // 2 x 128*40*2 = 20480
static constexpr int W1_STRIDE = 128 * LDW * 2;         // 10240
static constexpr int SM_W2    = 20480;                  // 2 bufs x 2 heads x 32*24*2 = 6144
static constexpr int W2_STRIDE = 2 * 32 * LD2 * 2;      // 3072
static constexpr int W2_HEAD  = 32 * LD2 * 2;           // 1536
static constexpr int SM_AST   = 26624;                  // A: 128*136*2 = 34816 (LIVE whole loop)
static constexpr int SM_B1H   = 61440;                  // 512 uints = 2048
static constexpr int SM_BIAS  = 63488;                  // 32 floats = 128
static constexpr int SM_RED   = 63616;                  // 8 floats
static constexpr int SM_TOTAL = 63648;                  // x3 CTAs = 190944 < 228KB
static constexpr int SM_MU    = 0;                      // overlay on dead W1 region after loop
static constexpr int SM_LV    = 10240;

__device__ __forceinline__ void load_w1_chunk_async(uint sb, int ch, int buf, int tid) {
    const char* src0 = (const char*)g_W1h + ch * 64;
    #pragma unroll
    for (int i = 0; i < 4; ++i) {
        int o = tid + 128 * i;                 // 0..511
        int row = o >> 2, seg = o & 3;
        const char* src = src0 + (size_t)row * 2048 + seg * 16;
        uint dst = sb + SM_W1 + buf * W1_STRIDE + row * (LDW * 2) + seg * 16;
        CP_ASYNC16(dst, src);
    }
}

__device__ __forceinline__ void load_w2_chunk_async(uint sb, int ch, int buf, int tid) {
    int head = tid >> 6, w = tid & 63;
    int row = w >> 1, seg = w & 1;
    const char* src = (const char*)(head ? g_Wlh : g_Wmh) + (size_t)(ch * 32 + row) * 32 + seg * 16;
    uint dst = sb + SM_W2 + buf * W2_STRIDE + head * W2_HEAD + row * (LD2 * 2) + seg * 16;
    CP_ASYNC16(dst, src);
}

__global__ __launch_bounds__(128, 3)
void k_main(const float* __restrict__ states, const float* __restrict__ actions,
            const float* __restrict__ blp,
            const float* __restrict__ bmu, const float* __restrict__ blv,
            float* __restrict__ out) {
    extern __shared__ char smem[];
    uint sb = smem_u32(smem);
    uint*  sB1h  = (uint*)(smem + SM_B1H);
    float* sBias = (float*)(smem + SM_BIAS);
    float* sRed  = (float*)(smem + SM_RED);

    int tid  = threadIdx.x;
    int warp = tid >> 5, lane = tid & 31;
    int r0   = blockIdx.x * RT;

    int lrow = lane & 15;
    int lcol = (lane >> 4) * 8;

    // prefetch W1/W2 chunks 0,1 FIRST (overlaps A staging below)
    load_w1_chunk_async(sb, 0, 0, tid);
    load_w2_chunk_async(sb, 0, 0, tid);
    CP_COMMIT();
    load_w1_chunk_async(sb, 1, 1, tid);
    load_w2_chunk_async(sb, 1, 1, tid);
    CP_COMMIT();

    if (tid < 16) { sBias[tid] = bmu[tid]; sBias[16 + tid] = blv[tid]; }
    ((uint4*)sB1h)[tid] = ((const uint4*)g_b1h)[tid];   // 512 uints

    // --- stage states tile [128 x 128] fp32->fp16 into AST (LDA=136, live) ---
    {
        half* sAst = (half*)(smem + SM_AST);
        const float4* st4 = (const float4*)states + (size_t)r0 * 32;
        #pragma unroll
        for (int it = 0; it < 32; ++it) {
            int idx = tid + 128 * it;
            int row = idx >> 5, c4 = idx & 31;
            float4 v = st4[row * 32 + c4];
            half2* dst = (half2*)(sAst + row * LDA + c4 * 4);
            dst[0] = __floats2half2_rn(v.x, v.y);
            dst[1] = __floats2half2_rn(v.z, v.w);
        }
    }

    float muL[2][4], muH[2][4], lvL[2][4], lvH[2][4];
    #pragma unroll
    for (int t = 0; t < 2; ++t)
        #pragma unroll
        for (int i = 0; i < 4; ++i) {
            muL[t][i] = 0.f; muH[t][i] = 0.f; lvL[t][i] = 0.f; lvH[t][i] = 0.f;
        }

    uint w1lane = sb + SM_W1 + (lrow * LDW + lcol) * 2;
    uint w2lane = sb + SM_W2 + (lrow * LD2 + lcol) * 2;
    uint abase0 = sb + SM_AST + ((warp * 32 + lrow) * LDA + lcol) * 2;
    uint abase1 = sb + SM_AST + ((warp * 32 + 16 + lrow) * LDA + lcol) * 2;

    for (int ch = 0; ch < NCH; ++ch) {
        int buf = ch & 1;
        if (ch + 1 < NCH) CP_WAIT1(); else CP_WAIT0();
        __syncthreads();   // covers cp.async chunk + (ch==0) AST staging

        uint w1b = w1lane + buf * W1_STRIDE;
        uint w2b = w2lane + buf * W2_STRIDE;
        const uint* b1c = sB1h + ch * 16 + (lane & 3);

        // --- GEMM1, software-pipelined: stage ks+1 loads before stage ks MMAs ---
        uint acc0[4][2], acc1[4][2];
        #pragma unroll
        for (int nt = 0; nt < 4; ++nt) {
            acc0[nt][0] = 0u; acc0[nt][1] = 0u;
            acc1[nt][0] = 0u; acc1[nt][1] = 0u;
        }
        uint aS[2][8], bS[2][8];
        // prologue: stage ks=0
        LDSM_X4(aS[0][0], aS[0][1], aS[0][2], aS[0][3], abase0);
        LDSM_X4(aS[0][4], aS[0][5], aS[0][6], aS[0][7], abase1);
        LDSM_X4T(bS[0][0], bS[0][1], bS[0][2], bS[0][3], w1b);
        LDSM_X4T(bS[0][4], bS[0][5], bS[0][6], bS[0][7], w1b + 32);
        #pragma unroll
        for (int ks = 0; ks < 8; ++ks) {
            int cur = ks & 1, nxt = cur ^ 1;
            if (ks < 7) {
                LDSM_X4(aS[nxt][0], aS[nxt][1], aS[nxt][2], aS[nxt][3], abase0 + (ks + 1) * 32);
                LDSM_X4(aS[nxt][4], aS[nxt][5], aS[nxt][6], aS[nxt][7], abase1 + (ks + 1) * 32);
                LDSM_X4T(bS[nxt][0], bS[nxt][1], bS[nxt][2], bS[nxt][3],
                         w1b + (ks + 1) * (16 * LDW * 2));
                LDSM_X4T(bS[nxt][4], bS[nxt][5], bS[nxt][6], bS[nxt][7],
                         w1b + (ks + 1) * (16 * LDW * 2) + 32);
            }
            MMA16816H(acc0[0], (aS[cur] + 0), bS[cur][0], bS[cur][1]);
            MMA16816H(acc0[1], (aS[cur] + 0), bS[cur][2], bS[cur][3]);
            MMA16816H(acc1[0], (aS[cur] + 4), bS[cur][0], bS[cur][1]);
            MMA16816H(acc1[1], (aS[cur] + 4), bS[cur][2], bS[cur][3]);
            MMA16816H(acc0[2], (aS[cur] + 0), bS[cur][4], bS[cur][5]);
            MMA16816H(acc0[3], (aS[cur] + 0), bS[cur][6], bS[cur][7]);
            MMA16816H(acc1[2], (aS[cur] + 4), bS[cur][4], bS[cur][5]);
            MMA16816H(acc1[3], (aS[cur] + 4), bS[cur][6], bS[cur][7]);
        }

        // --- epilogue: W2 LDSM first (independent), then tanh, then MMAs ---
        uint m0f[2][4], l0f[2][4];
        #pragma unroll
        for (int np = 0; np < 2; ++np) {
            LDSM_X4T(m0f[np][0], m0f[np][1], m0f[np][2], m0f[np][3],
                     w2b + np * (16 * LD2 * 2));
            LDSM_X4T(l0f[np][0], l0f[np][1], l0f[np][2], l0f[np][3],
                     w2b + W2_HEAD + np * (16 * LD2 * 2));
        }
        uint a2[2][2][4];   // [np][tile][frag]
        #pragma unroll
        for (int np = 0; np < 2; ++np) {
            uint be = b1c[np * 8];
            uint bo = b1c[np * 8 + 4];
            a2[np][0][0] = htanh2(hadd2u(acc0[2 * np][0],     be));
            a2[np][0][1] = htanh2(hadd2u(acc0[2 * np][1],     be));
            a2[np][0][2] = htanh2(hadd2u(acc0[2 * np + 1][0], bo));
            a2[np][0][3] = htanh2(hadd2u(acc0[2 * np + 1][1], bo));
            a2[np][1][0] = htanh2(hadd2u(acc1[2 * np][0],     be));
            a2[np][1][1] = htanh2(hadd2u(acc1[2 * np][1],     be));
            a2[np][1][2] = htanh2(hadd2u(acc1[2 * np + 1][0], bo));
            a2[np][1][3] = htanh2(hadd2u(acc1[2 * np + 1][1], bo));
        }
        #pragma unroll
        for (int np = 0; np < 2; ++np) {
            MMA16816(muL[0], a2[np][0], m0f[np][0], m0f[np][1]);
            MMA16816(muH[0], a2[np][0], m0f[np][2], m0f[np][3]);
            MMA16816(muL[1], a2[np][1], m0f[np][0], m0f[np][1]);
            MMA16816(muH[1], a2[np][1], m0f[np][2], m0f[np][3]);
            MMA16816(lvL[0], a2[np][0], l0f[np][0], l0f[np][1]);
            MMA16816(lvH[0], a2[np][0], l0f[np][2], l0f[np][3]);
            MMA16816(lvL[1], a2[np][1], l0f[np][0], l0f[np][1]);
            MMA16816(lvH[1], a2[np][1], l0f[np][2], l0f[np][3]);
        }

        __syncthreads();
        if (ch + 2 < NCH) {
            load_w1_chunk_async(sb, ch + 2, buf, tid);
            load_w2_chunk_async(sb, ch + 2, buf, tid);
            CP_COMMIT();
        }
    }

    // --- dump mu/lv to overlay (W1 region dead after loop) ---
    __syncthreads();
    {
        float* sMu = (float*)(smem + SM_MU);
        float* sLv = (float*)(smem + SM_LV);
        int cc = (lane & 3) * 2;
        #pragma unroll
        for (int t = 0; t < 2; ++t) {
            int rr = warp * 32 + t * 16 + (lane >> 2);
            float* mu = (t == 0) ? muL[0] : muL[1];
            float* mh = (t == 0) ? muH[0] : muH[1];
            float* lv = (t == 0) ? lvL[0] : lvL[1];
            float* lh = (t == 0) ? lvH[0] : lvH[1];
            *(float2*)&sMu[rr * LDMU + cc]           = make_float2(mu[0], mu[1]);
            *(float2*)&sMu[(rr + 8) * LDMU + cc]     = make_float2(mu[2], mu[3]);
            *(float2*)&sMu[rr * LDMU + cc + 8]       = make_float2(mh[0], mh[1]);
            *(float2*)&sMu[(rr + 8) * LDMU + cc + 8] = make_float2(mh[2], mh[3]);
            *(float2*)&sLv[rr * LDMU + cc]           = make_float2(lv[0], lv[1]);
            *(float2*)&sLv[(rr + 8) * LDMU + cc]     = make_float2(lv[2], lv[3]);
            *(float2*)&sLv[rr * LDMU + cc + 8]       = make_float2(lh[0], lh[1]);
            *(float2*)&sLv[(rr + 8) * LDMU + cc + 8] = make_float2(lh[2], lh[3]);
        }
    }
    __syncthreads();

    // --- loss epilogue: each thread owns one row ---
    const float* sMu = (const float*)(smem + SM_MU);
    const float* sLv = (const float*)(smem + SM_LV);
    int gr = r0 + tid;
    const float4* a4 = (const float4*)(actions + (size_t)gr * A);
    const float4* p4 = (const float4*)(blp + (size_t)gr * A);
    float lsum = 0.f;
    #pragma unroll
    for (int q = 0; q < 4; ++q) {
        float4 av = a4[q];
        float4 bv = p4[q];
        float aarr[4] = {av.x, av.y, av.z, av.w};
        float barr[4] = {bv.x, bv.y, bv.z, bv.w};
        #pragma unroll
        for (int j = 0; j < 4; ++j) {
            int col = q * 4 + j;
            float mu = sMu[tid * LDMU + col] + sBias[col];
            float lv = sLv[tid * LDMU + col] + sBias[16 + col];
            float d  = aarr[j] - mu;
            float logp = -0.5f * d * d * __expf(-lv) - 0.5f * lv - LOG_SQRT_2PI;
            lsum += logp - barr[j];
        }
    }
    float ratio = __expf(lsum);
    float ahat  = (g_adv[gr] - g_mean) * g_inv;
    float rc    = fminf(fmaxf(ratio, 1.f - EPSC), 1.f + EPSC);
    float term  = fminf(ratio * ahat, rc * ahat);

    #pragma unroll
    for (int o = 16; o > 0; o >>= 1) term += __shfl_down_sync(0xffffffffu, term, o);
    if ((tid & 31) == 0) sRed[warp] = term;
    __syncthreads();
    if (tid == 0) {
        float bsum = sRed[0] + sRed[1] + sRed[2] + sRed[3];
        atomicAdd(&g_actor, bsum);
        __threadfence();
        uint done = atomicAdd(&g_cnt_main, 1u);
        if (done == (uint)(gridDim.x - 1)) {
            float actor = atomicAdd(&g_actor, 0.f);
            out[0] = g_critic - actor / (float)T;
        }
    }
}

// ---------------- launch ----------------
extern "C" void kernel_launch(void* const* d_in, const int* in_sizes, int n_in,
                              void* d_out, int out_size) {
    const float* states  = (const float*)d_in[0];
    const float* actions = (const float*)d_in[1];
    const float* rewards = (const float*)d_in[2];
    const float* values  = (const float*)d_in[3];
    const float* blp     = (const float*)d_in[4];
    const float* W1      = (const float*)d_in[5];
    const float* b1      = (const float*)d_in[6];
    const float* Wmu     = (const float*)d_in[7];
    const float* bmu     = (const float*)d_in[8];
    const float* Wlv     = (const float*)d_in[9];
    const float* blv     = (const float*)d_in[10];
    const int*   masks   = (const int*)d_in[11];

    cudaFuncSetAttribute(k_main, cudaFuncAttributeMaxDynamicSharedMemorySize, SM_TOTAL);

    k_prep<<<512, 256>>>(W1, Wmu, Wlv, b1);
    k_scan1<<<256, 256>>>(rewards, masks);
    k_scan3<<<256, 256>>>(rewards, masks, values);
    k_main<<<T / RT, 128, SM_TOTAL>>>(states, actions, blp, bmu, blv, (float*)d_out);
}

// round 17
// speedup vs baseline: 1.1270x; 1.1270x over previous
#include <cuda_runtime.h>
#include <cuda_fp16.h>

typedef unsigned int uint;

static constexpr int   T = 262144;
static constexpr int   S = 128;
static constexpr int   H = 1024;
static constexpr int   A = 16;
static constexpr float GAMMA = 0.99f;
static constexpr float EPSC  = 0.2f;
static constexpr float LOG_SQRT_2PI = 0.91893853320467274178f;

// ---------------- device scratch (no allocation allowed) ----------------
__device__ float g_adv[T];
__device__ float g_blockA[256];
__device__ float g_blockB[256];
__device__ float g_s1, g_s2, g_actor;
__device__ float g_mean, g_inv, g_critic;
__device__ uint  g_cnt_scan, g_cnt_main;
__device__ __half g_W1h[S * H];     // [k][h]  fp16 copy of W1
__device__ __half g_Wmh[H * A];     // [h][a]
__device__ __half g_Wlh[H * A];     // [h][a]
__device__ uint   g_b1h[H / 2];     // b1 packed as half2 pairs

// ---------------- helpers ----------------
__device__ __forceinline__ uint smem_u32(const void* p) {
    uint a;
    asm("{ .reg .u64 t; cvta.to.shared.u64 t, %1; cvt.u32.u64 %0, t; }" : "=r"(a) : "l"(p));
    return a;
}

#define CP_ASYNC16(dst, src) \
    asm volatile("cp.async.cg.shared.global [%0], [%1], 16;" :: "r"(dst), "l"(src))
#define CP_COMMIT() asm volatile("cp.async.commit_group;" ::: "memory")
#define CP_WAIT1()  asm volatile("cp.async.wait_group 1;" ::: "memory")
#define CP_WAIT0()  asm volatile("cp.async.wait_group 0;" ::: "memory")

#define LDSM_X4(r0, r1, r2, r3, addr) \
    asm volatile("ldmatrix.sync.aligned.m8n8.x4.shared.b16 {%0,%1,%2,%3}, [%4];" \
        : "=r"(r0), "=r"(r1), "=r"(r2), "=r"(r3) : "r"(addr))
#define LDSM_X4T(r0, r1, r2, r3, addr) \
    asm volatile("ldmatrix.sync.aligned.m8n8.x4.trans.shared.b16 {%0,%1,%2,%3}, [%4];" \
        : "=r"(r0), "=r"(r1), "=r"(r2), "=r"(r3) : "r"(addr))

// fp32-accumulate mma (GEMM2)
#define MMA16816(d, a, b0, b1) \
    asm volatile("mma.sync.aligned.m16n8k16.row.col.f32.f16.f16.f32 " \
        "{%0,%1,%2,%3}, {%4,%5,%6,%7}, {%8,%9}, {%0,%1,%2,%3};" \
        : "+f"((d)[0]), "+f"((d)[1]), "+f"((d)[2]), "+f"((d)[3]) \
        : "r"((a)[0]), "r"((a)[1]), "r"((a)[2]), "r"((a)[3]), "r"(b0), "r"(b1))

// fp16-accumulate mma (GEMM1; fewer acc regs)
#define MMA16816H(d, a, b0, b1) \
    asm volatile("mma.sync.aligned.m16n8k16.row.col.f16.f16.f16.f16 " \
        "{%0,%1}, {%2,%3,%4,%5}, {%6,%7}, {%0,%1};" \
        : "+r"((d)[0]), "+r"((d)[1]) \
        : "r"((a)[0]), "r"((a)[1]), "r"((a)[2]), "r"((a)[3]), "r"(b0), "r"(b1))

__device__ __forceinline__ uint htanh2(uint x) {
    uint y; asm("tanh.approx.f16x2 %0, %1;" : "=r"(y) : "r"(x)); return y;
}
__device__ __forceinline__ uint hadd2u(uint x, uint y) {
    uint z; asm("add.f16x2 %0, %1, %2;" : "=r"(z) : "r"(x), "r"(y)); return z;
}

// ---------------- Kp: (merged) weight convert + per-block scan summaries --------
__global__ void k_prep_scan1(const float* __restrict__ W1, const float* __restrict__ Wmu,
                             const float* __restrict__ Wlv, const float* __restrict__ b1,
                             const float* __restrict__ rewards, const int* __restrict__ masks) {
    if (blockIdx.x < 512) {
        int idx = blockIdx.x * 256 + threadIdx.x;     // 0 .. 131071
        g_W1h[idx] = __float2half_rn(W1[idx]);
        if (idx < H * A) {
            g_Wmh[idx] = __float2half_rn(Wmu[idx]);
            g_Wlh[idx] = __float2half_rn(Wlv[idx]);
        }
        if (idx < H / 2) {
            half2 p = __floats2half2_rn(b1[2 * idx], b1[2 * idx + 1]);
            g_b1h[idx] = *(uint*)&p;
        }
        if (idx == 0) {
            g_s1 = 0.f; g_s2 = 0.f; g_actor = 0.f;
            g_cnt_scan = 0u; g_cnt_main = 0u;
        }
        return;
    }
    // scan1 part: blocks 512..767
    int blk = blockIdx.x - 512, tid = threadIdx.x;
    int base = blk * 1024 + tid * 4;
    float4 r = *(const float4*)(rewards + base);
    int4   m = *(const int4*)(masks + base);
    float a = 1.f, b = 0.f, c;
    c = GAMMA * (float)m.w; b = r.w + c * b; a *= c;
    c = GAMMA * (float)m.z; b = r.z + c * b; a *= c;
    c = GAMMA * (float)m.y; b = r.y + c * b; a *= c;
    c = GAMMA * (float)m.x; b = r.x + c * b; a *= c;
    __shared__ float sA[256], sB[256];
    sA[tid] = a; sB[tid] = b;
    __syncthreads();
    #pragma unroll
    for (int o = 1; o < 256; o <<= 1) {
        float na = a, nb = b;
        if (tid + o < 256) { na = a * sA[tid + o]; nb = b + a * sB[tid + o]; }
        __syncthreads();
        sA[tid] = na; sB[tid] = nb; a = na; b = nb;
        __syncthreads();
    }
    if (tid == 0) { g_blockA[blk] = a; g_blockB[blk] = b; }
}

// ---------------- K2: apply scan + adv + sums + (last block) stats ----------------
__global__ void k_scan3(const float* __restrict__ rewards, const int* __restrict__ masks,
                        const float* __restrict__ values) {
    int blk = blockIdx.x, tid = threadIdx.x;
    int base = blk * 1024 + tid * 4;
    float4 r = *(const float4*)(rewards + base);
    int4   m = *(const int4*)(masks + base);
    float c0 = GAMMA * (float)m.x, c1 = GAMMA * (float)m.y;
    float c2 = GAMMA * (float)m.z, c3 = GAMMA * (float)m.w;
    float a = 1.f, b = 0.f;
    b = r.w + c3 * b; a *= c3;
    b = r.z + c2 * b; a *= c2;
    b = r.y + c1 * b; a *= c1;
    b = r.x + c0 * b; a *= c0;

    __shared__ float sA[256], sB[256];
    __shared__ float red8[8];

    float ga = g_blockA[tid], gb = g_blockB[tid];
    sA[tid] = ga; sB[tid] = gb;
    __syncthreads();
    #pragma unroll
    for (int o = 1; o < 256; o <<= 1) {
        float na = ga, nb = gb;
        if (tid + o < 256) { na = ga * sA[tid + o]; nb = gb + ga * sB[tid + o]; }
        __syncthreads();
        sA[tid] = na; sB[tid] = nb; ga = na; gb = nb;
        __syncthreads();
    }
    float inc = (blk < 255) ? sB[blk + 1] : 0.f;
    __syncthreads();

    float qa = a, qb = b;
    sA[tid] = qa; sB[tid] = qb;
    __syncthreads();
    #pragma unroll
    for (int o = 1; o < 256; o <<= 1) {
        float na = qa, nb = qb;
        if (tid + o < 256) { na = qa * sA[tid + o]; nb = qb + qa * sB[tid + o]; }
        __syncthreads();
        sA[tid] = na; sB[tid] = nb; qa = na; qb = nb;
        __syncthreads();
    }
    float x = (tid < 255) ? (sA[tid + 1] * inc + sB[tid + 1]) : inc;

    float ret3 = r.w + c3 * x;
    float ret2 = r.z + c2 * ret3;
    float ret1 = r.y + c1 * ret2;
    float ret0 = r.x + c0 * ret1;
    float4 v = *(const float4*)(values + base);
    float4 adv = make_float4(ret0 - v.x, ret1 - v.y, ret2 - v.z, ret3 - v.w);
    *(float4*)(g_adv + base) = adv;
    float s1 = adv.x + adv.y + adv.z + adv.w;
    float s2 = adv.x * adv.x + adv.y * adv.y + adv.z * adv.z + adv.w * adv.w;

    #pragma unroll
    for (int o = 16; o > 0; o >>= 1) {
        s1 += __shfl_down_sync(0xffffffffu, s1, o);
        s2 += __shfl_down_sync(0xffffffffu, s2, o);
    }
    if ((tid & 31) == 0) { red8[tid >> 5] = s1; }
    __syncthreads();
    if ((tid & 31) == 0) { sA[tid >> 5] = s2; }
    __syncthreads();
    if (tid == 0) {
        float t1 = 0.f, t2 = 0.f;
        #pragma unroll
        for (int i = 0; i < 8; ++i) { t1 += red8[i]; t2 += sA[i]; }
        atomicAdd(&g_s1, t1);
        atomicAdd(&g_s2, t2);
        __threadfence();
        uint done = atomicAdd(&g_cnt_scan, 1u);
        if (done == 255u) {
            float S1 = atomicAdd(&g_s1, 0.f);
            float S2 = atomicAdd(&g_s2, 0.f);
            float mean = S1 / (float)T;
            float var  = (S2 - S1 * mean) / (float)(T - 1);
            g_mean = mean;
            g_inv  = 1.f / (sqrtf(var) + 1e-7f);
            g_critic = S2 / (float)T;
        }
    }
}

// ---------------- K5: R11 config + CTA-parity chunk stagger ----------------
static constexpr int RT  = 128;      // rows per CTA (4 warps x 32 rows)
static constexpr int NCH = 16;       // H chunks of 64
static constexpr int LDA = 136;      // staging stride (halves)
static constexpr int LDW = 72;       // W1 smem stride (halves)
static constexpr int LD2 = 24;       // W2 smem stride (halves)
static constexpr int LDMU = 20;      // mu/lv overlay stride (floats)

static constexpr int SM_W1    = 0;                      // 2 x 128*72*2 = 36864 (A-stage overlays)
static constexpr int W1_STRIDE = 128 * LDW * 2;         // 18432
static constexpr int SM_W2    = 36864;                  // 2 bufs x 2 heads x 64*24*2 = 12288
static constexpr int W2_STRIDE = 2 * 64 * LD2 * 2;      // 6144
static constexpr int W2_HEAD  = 64 * LD2 * 2;           // 3072
static constexpr int SM_B1H   = 49152;                  // 512 uints = 2048
static constexpr int SM_BIAS  = 51200;                  // 32 floats
static constexpr int SM_RED   = 51328;                  // 8 floats
static constexpr int SM_TOTAL = 51456;
static constexpr int SM_MU    = 0;                      // overlay on dead W1 region
static constexpr int SM_LV    = 10240;

__device__ __forceinline__ void load_w1_chunk_async(uint sb, int ch, int buf, int tid) {
    const char* src0 = (const char*)g_W1h + ch * 128;   // + row*2048 + seg*16
    #pragma unroll
    for (int i = 0; i < 8; ++i) {
        int o = tid + 128 * i;                 // 0..1023
        int row = o >> 3, seg = o & 7;
        const char* src = src0 + (size_t)row * 2048 + seg * 16;
        uint dst = sb + SM_W1 + buf * W1_STRIDE + row * (LDW * 2) + seg * 16;
        CP_ASYNC16(dst, src);
    }
}

__device__ __forceinline__ void load_w2_chunk_async(uint sb, int ch, int buf, int tid) {
    #pragma unroll
    for (int i = 0; i < 2; ++i) {
        int o = tid + 128 * i;                 // 0..255
        int head = o >> 7, w = o & 127;
        int row = w >> 1, seg = w & 1;
        const char* src = (const char*)(head ? g_Wlh : g_Wmh) + (size_t)(ch * 64 + row) * 32 + seg * 16;
        uint dst = sb + SM_W2 + buf * W2_STRIDE + head * W2_HEAD + row * (LD2 * 2) + seg * 16;
        CP_ASYNC16(dst, src);
    }
}

__global__ __launch_bounds__(128, 2)
void k_main(const float* __restrict__ states, const float* __restrict__ actions,
            const float* __restrict__ blp,
            const float* __restrict__ bmu, const float* __restrict__ blv,
            float* __restrict__ out) {
    extern __shared__ char smem[];
    uint sb = smem_u32(smem);
    uint*  sB1h  = (uint*)(smem + SM_B1H);
    float* sBias = (float*)(smem + SM_BIAS);
    float* sRed  = (float*)(smem + SM_RED);

    int tid  = threadIdx.x;
    int warp = tid >> 5, lane = tid & 31;
    int r0   = blockIdx.x * RT;
    int off  = (blockIdx.x & 1) * (NCH / 2);   // phase stagger by CTA parity

    int lrow = lane & 15;
    int lcol = (lane >> 4) * 8;

    if (tid < 16) { sBias[tid] = bmu[tid]; sBias[16 + tid] = blv[tid]; }
    ((uint4*)sB1h)[tid] = ((const uint4*)g_b1h)[tid];   // 512 uints

    // --- stage states tile [128 x 128] fp32->fp16 into W1 region ---
    {
        half* sAst = (half*)(smem + SM_W1);
        const float4* st4 = (const float4*)states + (size_t)r0 * 32;
        #pragma unroll
        for (int it = 0; it < 32; ++it) {
            int idx = tid + 128 * it;
            int row = idx >> 5, c4 = idx & 31;
            float4 v = st4[row * 32 + c4];
            half2* dst = (half2*)(sAst + row * LDA + c4 * 4);
            dst[0] = __floats2half2_rn(v.x, v.y);
            dst[1] = __floats2half2_rn(v.z, v.w);
        }
    }
    __syncthreads();

    // --- A fragments: 32 rows per warp, resident in registers ---
    uint afr[2][8][4];
    #pragma unroll
    for (int t = 0; t < 2; ++t) {
        uint abase = sb + SM_W1 + ((warp * 32 + t * 16 + lrow) * LDA + lcol) * 2;
        #pragma unroll
        for (int ks = 0; ks < 8; ++ks)
            LDSM_X4(afr[t][ks][0], afr[t][ks][1], afr[t][ks][2], afr[t][ks][3], abase + ks * 32);
    }
    __syncthreads();

    // --- prefetch chunks off, off+1 ---
    load_w1_chunk_async(sb, off, 0, tid);
    load_w2_chunk_async(sb, off, 0, tid);
    CP_COMMIT();
    load_w1_chunk_async(sb, (off + 1) & (NCH - 1), 1, tid);
    load_w2_chunk_async(sb, (off + 1) & (NCH - 1), 1, tid);
    CP_COMMIT();

    float muL[2][4], muH[2][4], lvL[2][4], lvH[2][4];
    #pragma unroll
    for (int t = 0; t < 2; ++t)
        #pragma unroll
        for (int i = 0; i < 4; ++i) {
            muL[t][i] = 0.f; muH[t][i] = 0.f; lvL[t][i] = 0.f; lvH[t][i] = 0.f;
        }

    uint w1lane = sb + SM_W1 + (lrow * LDW + lcol) * 2;
    uint w2lane = sb + SM_W2 + (lrow * LD2 + lcol) * 2;

    for (int ch = 0; ch < NCH; ++ch) {
        int buf = ch & 1;
        int co  = (ch + off) & (NCH - 1);       // staggered chunk index
        if (ch + 1 < NCH) CP_WAIT1(); else CP_WAIT0();
        __syncthreads();

        // --- GEMM1 (f16 acc): two row-tiles share every B fragment ---
        uint acc0[8][2], acc1[8][2];
        #pragma unroll
        for (int nt = 0; nt < 8; ++nt) {
            acc0[nt][0] = 0u; acc0[nt][1] = 0u;
            acc1[nt][0] = 0u; acc1[nt][1] = 0u;
        }
        uint w1b = w1lane + buf * W1_STRIDE;
        #pragma unroll
        for (int ks = 0; ks < 8; ++ks) {
            #pragma unroll
            for (int np = 0; np < 4; ++np) {
                uint b0, b1r, b2, b3;
                LDSM_X4T(b0, b1r, b2, b3, w1b + ks * (16 * LDW * 2) + np * 32);
                MMA16816H(acc0[2 * np],     afr[0][ks], b0, b1r);
                MMA16816H(acc0[2 * np + 1], afr[0][ks], b2, b3);
                MMA16816H(acc1[2 * np],     afr[1][ks], b0, b1r);
                MMA16816H(acc1[2 * np + 1], afr[1][ks], b2, b3);
            }
        }

        // --- epilogue: HADD2 bias + tanh.f16x2 -> A fragments; GEMM2 fp32 acc ---
        const uint* b1c = sB1h + co * 32 + (lane & 3);
        uint w2b = w2lane + buf * W2_STRIDE;
        #pragma unroll
        for (int np = 0; np < 4; ++np) {
            uint be = b1c[np * 8];
            uint bo = b1c[np * 8 + 4];
            uint a20[4], a21[4];
            a20[0] = htanh2(hadd2u(acc0[2 * np][0],     be));
            a20[1] = htanh2(hadd2u(acc0[2 * np][1],     be));
            a20[2] = htanh2(hadd2u(acc0[2 * np + 1][0], bo));
            a20[3] = htanh2(hadd2u(acc0[2 * np + 1][1], bo));
            a21[0] = htanh2(hadd2u(acc1[2 * np][0],     be));
            a21[1] = htanh2(hadd2u(acc1[2 * np][1],     be));
            a21[2] = htanh2(hadd2u(acc1[2 * np + 1][0], bo));
            a21[3] = htanh2(hadd2u(acc1[2 * np + 1][1], bo));

            uint m0, m1, m2, m3;
            LDSM_X4T(m0, m1, m2, m3, w2b + np * (16 * LD2 * 2));
            MMA16816(muL[0], a20, m0, m1);
            MMA16816(muH[0], a20, m2, m3);
            MMA16816(muL[1], a21, m0, m1);
            MMA16816(muH[1], a21, m2, m3);
            uint l0, l1, l2, l3;
            LDSM_X4T(l0, l1, l2, l3, w2b + W2_HEAD + np * (16 * LD2 * 2));
            MMA16816(lvL[0], a20, l0, l1);
            MMA16816(lvH[0], a20, l2, l3);
            MMA16816(lvL[1], a21, l0, l1);
            MMA16816(lvH[1], a21, l2, l3);
        }

        __syncthreads();
        if (ch + 2 < NCH) {
            int cn = (ch + 2 + off) & (NCH - 1);
            load_w1_chunk_async(sb, cn, buf, tid);
            load_w2_chunk_async(sb, cn, buf, tid);
            CP_COMMIT();
        }
    }

    // --- dump mu/lv to overlay (W1 region dead) ---
    __syncthreads();
    {
        float* sMu = (float*)(smem + SM_MU);
        float* sLv = (float*)(smem + SM_LV);
        int cc = (lane & 3) * 2;
        #pragma unroll
        for (int t = 0; t < 2; ++t) {
            int rr = warp * 32 + t * 16 + (lane >> 2);
            *(float2*)&sMu[rr * LDMU + cc]           = make_float2(muL[t][0], muL[t][1]);
            *(float2*)&sMu[(rr + 8) * LDMU + cc]     = make_float2(muL[t][2], muL[t][3]);
            *(float2*)&sMu[rr * LDMU + cc + 8]       = make_float2(muH[t][0], muH[t][1]);
            *(float2*)&sMu[(rr + 8) * LDMU + cc + 8] = make_float2(muH[t][2], muH[t][3]);
            *(float2*)&sLv[rr * LDMU + cc]           = make_float2(lvL[t][0], lvL[t][1]);
            *(float2*)&sLv[(rr + 8) * LDMU + cc]     = make_float2(lvL[t][2], lvL[t][3]);
            *(float2*)&sLv[rr * LDMU + cc + 8]       = make_float2(lvH[t][0], lvH[t][1]);
            *(float2*)&sLv[(rr + 8) * LDMU + cc + 8] = make_float2(lvH[t][2], lvH[t][3]);
        }
    }
    __syncthreads();

    // --- loss epilogue: each thread owns one row ---
    const float* sMu = (const float*)(smem + SM_MU);
    const float* sLv = (const float*)(smem + SM_LV);
    int gr = r0 + tid;
    const float4* a4 = (const float4*)(actions + (size_t)gr * A);
    const float4* p4 = (const float4*)(blp + (size_t)gr * A);
    float lsum = 0.f;
    #pragma unroll
    for (int q = 0; q < 4; ++q) {
        float4 av = a4[q];
        float4 bv = p4[q];
        float aarr[4] = {av.x, av.y, av.z, av.w};
        float barr[4] = {bv.x, bv.y, bv.z, bv.w};
        #pragma unroll
        for (int j = 0; j < 4; ++j) {
            int col = q * 4 + j;
            float mu = sMu[tid * LDMU + col] + sBias[col];
            float lv = sLv[tid * LDMU + col] + sBias[16 + col];
            float d  = aarr[j] - mu;
            float logp = -0.5f * d * d * __expf(-lv) - 0.5f * lv - LOG_SQRT_2PI;
            lsum += logp - barr[j];
        }
    }
    float ratio = __expf(lsum);
    float ahat  = (g_adv[gr] - g_mean) * g_inv;
    float rc    = fminf(fmaxf(ratio, 1.f - EPSC), 1.f + EPSC);
    float term  = fminf(ratio * ahat, rc * ahat);

    #pragma unroll
    for (int o = 16; o > 0; o >>= 1) term += __shfl_down_sync(0xffffffffu, term, o);
    if ((tid & 31) == 0) sRed[warp] = term;
    __syncthreads();
    if (tid == 0) {
        float bsum = sRed[0] + sRed[1] + sRed[2] + sRed[3];
        atomicAdd(&g_actor, bsum);
        __threadfence();
        uint done = atomicAdd(&g_cnt_main, 1u);
        if (done == (uint)(gridDim.x - 1)) {
            float actor = atomicAdd(&g_actor, 0.f);
            out[0] = g_critic - actor / (float)T;
        }
    }
}

// ---------------- launch ----------------
extern "C" void kernel_launch(void* const* d_in, const int* in_sizes, int n_in,
                              void* d_out, int out_size) {
    const float* states  = (const float*)d_in[0];
    const float* actions = (const float*)d_in[1];
    const float* rewards = (const float*)d_in[2];
    const float* values  = (const float*)d_in[3];
    const float* blp     = (const float*)d_in[4];
    const float* W1      = (const float*)d_in[5];
    const float* b1      = (const float*)d_in[6];
    const float* Wmu     = (const float*)d_in[7];
    const float* bmu     = (const float*)d_in[8];
    const float* Wlv     = (const float*)d_in[9];
    const float* blv     = (const float*)d_in[10];
    const int*   masks   = (const int*)d_in[11];

    cudaFuncSetAttribute(k_main, cudaFuncAttributeMaxDynamicSharedMemorySize, SM_TOTAL);

    k_prep_scan1<<<768, 256>>>(W1, Wmu, Wlv, b1, rewards, masks);
    k_scan3<<<256, 256>>>(rewards, masks, values);
    k_main<<<T / RT, 128, SM_TOTAL>>>(states, actions, blp, bmu, blv, (float*)d_out);
}